// round 4
// baseline (speedup 1.0000x reference)
#include <cuda_runtime.h>

// ---------------------------------------------------------------------------
// RoutingStorage (GR4J routing). FIR convolutions feed a nonlinear scalar
// recurrence on the routing store r; chunk-parallel scan with warmup.
// This round: 2 independent chains interleaved per thread (fills the
// dependency-stall issue slots — only 256 warps exist for 592 schedulers, so
// ILP must come from within the thread), uniform step count via zero-padded
// conv buffer, deg-3 poly on the off-critical gw branch.
// ---------------------------------------------------------------------------

#define T_MAX 262144
constexpr int CHUNK_L = 32;   // output steps per chain
constexpr int WARMUP  = 320;  // warmup steps (contraction ~0.951/step)
constexpr int UNROLL  = 4;
#define PAD 8

// Front-padded with WARMUP zeros: index i corresponds to t = i - WARMUP.
// Zero input keeps r exactly 0 (matches reference init), so every chain runs
// a uniform WARMUP+CHUNK_L steps with no branches.
static __device__ float2 g_conv[WARMUP + T_MAX + PAD];

__device__ __forceinline__ float fsqrt_approx(float x) {
    float y; asm("sqrt.approx.f32 %0, %1;" : "=f"(y) : "f"(x)); return y;
}

// Unit-hydrograph ordinates for X4 = 2.5:
__constant__ float c_o1[3] = {0.10119288512538814f, 0.47124051711455807f,
                              0.42756659776005380f};
__constant__ float c_o2[6] = {0.05059644256269407f, 0.23562025855727903f,
                              0.42756659776005380f, 0.23562025855727903f,
                              0.05059644256269407f, 0.0f};

__global__ void conv_kernel(const float* __restrict__ x, int T) {
    int i = blockIdx.x * blockDim.x + threadIdx.x;
    if (i >= WARMUP + T + PAD) return;
    int t = i - WARMUP;
    if (t < 0 || t >= T) { g_conv[i] = make_float2(0.0f, 0.0f); return; }
    float c1 = 0.0f, c2 = 0.0f;
#pragma unroll
    for (int j = 0; j < 6; ++j) {
        int idx = t - j;
        if (idx >= 0) {
            float4 row = *reinterpret_cast<const float4*>(x + 4 * idx);
            float pr = row.w + (row.x - row.z);   // perc + (p_n - p_s)
            if (j < 3) c1 += c_o1[j] * (0.9f * pr);
            c2 += c_o2[j] * (0.1f * pr);
        }
    }
    g_conv[i] = make_float2(c1, c2);
}

// (1+u)^(-1/4) deg-4 Horner
#define P1 (-0.25f)
#define P2 ( 0.15625f)
#define P3 (-0.1171875f)
#define P4 ( 0.0952148438f)
// (1+u)^(-7/8) deg-3 Horner (off-critical gw branch)
#define Q1 (-0.875f)
#define Q2 ( 0.8203125f)
#define Q3 (-0.7861328125f)

template<bool STORE>
__device__ __forceinline__ void step_one(float& r, float& gw,
                                         float c1, float c2,
                                         float x2, float inv, float inv4,
                                         float* qp, float* rp) {
    float s  = fmaxf((r + c1) + gw, 0.0f);
    float s2 = s * s;
    float u  = (s2 * inv4) * s2;                  // (s/x3)^4
    float p  = fmaf(u, P4, P3); p = fmaf(u, p, P2);
    p = fmaf(u, p, P1); p = fmaf(u, p, 1.0f);     // (1+u)^(-1/4)
    float rn = s * p;
    float qq = fmaf(u, Q3, Q2);
    qq = fmaf(u, qq, Q1); qq = fmaf(u, qq, 1.0f); // (1+u)^(-7/8)
    float v  = s * inv;
    float sv = fsqrt_approx(v);
    float gs = (x2 * ((v * v) * v)) * sv;         // x2*(s/x3)^3.5
    if (STORE) {
        float qd = fmaxf(c2 + gw, 0.0f);
        *qp = (s - rn) + qd;
        *rp = rn;
    }
    r  = rn;
    gw = gs * qq;                                 // x2*(rn/x3)^3.5
}

__global__ void scan_kernel(const float* __restrict__ x2p,
                            const float* __restrict__ x3p,
                            float* __restrict__ out, int T) {
    int pair = blockIdx.x * blockDim.x + threadIdx.x;
    int C = T / CHUNK_L;                 // T is a multiple of CHUNK_L here
    int a = 2 * pair;
    if (a >= C) return;
    int b = a + 1; if (b >= C) b = a;    // degenerate tail: duplicate work, same stores

    const float x2  = __ldg(x2p);
    const float x3  = __ldg(x3p);
    const float inv = 1.0f / x3;
    float inv2 = inv * inv, inv4 = inv2 * inv2;

    float* __restrict__ qout = out;       // qsim    [0, T)
    float* __restrict__ rout = out + T;   // r_store [T, 2T)

    const float2* __restrict__ pA = g_conv + a * CHUNK_L;
    const float2* __restrict__ pB = g_conv + b * CHUNK_L;

    float rA = 0.0f, gwA = 0.0f;
    float rB = 0.0f, gwB = 0.0f;

    // Warmup: interleaved, no stores (dead q path is DCE'd).
    for (int i = 0; i < WARMUP; i += UNROLL) {
        float4 a01 = *reinterpret_cast<const float4*>(pA + i);
        float4 a23 = *reinterpret_cast<const float4*>(pA + i + 2);
        float4 b01 = *reinterpret_cast<const float4*>(pB + i);
        float4 b23 = *reinterpret_cast<const float4*>(pB + i + 2);
        step_one<false>(rA, gwA, a01.x, a01.y, x2, inv, inv4, nullptr, nullptr);
        step_one<false>(rB, gwB, b01.x, b01.y, x2, inv, inv4, nullptr, nullptr);
        step_one<false>(rA, gwA, a01.z, a01.w, x2, inv, inv4, nullptr, nullptr);
        step_one<false>(rB, gwB, b01.z, b01.w, x2, inv, inv4, nullptr, nullptr);
        step_one<false>(rA, gwA, a23.x, a23.y, x2, inv, inv4, nullptr, nullptr);
        step_one<false>(rB, gwB, b23.x, b23.y, x2, inv, inv4, nullptr, nullptr);
        step_one<false>(rA, gwA, a23.z, a23.w, x2, inv, inv4, nullptr, nullptr);
        step_one<false>(rB, gwB, b23.z, b23.w, x2, inv, inv4, nullptr, nullptr);
    }

    // Output phase.
    int tA = a * CHUNK_L, tB = b * CHUNK_L;
    for (int i = WARMUP; i < WARMUP + CHUNK_L; i += UNROLL) {
        float4 a01 = *reinterpret_cast<const float4*>(pA + i);
        float4 a23 = *reinterpret_cast<const float4*>(pA + i + 2);
        float4 b01 = *reinterpret_cast<const float4*>(pB + i);
        float4 b23 = *reinterpret_cast<const float4*>(pB + i + 2);
        step_one<true>(rA, gwA, a01.x, a01.y, x2, inv, inv4, qout + tA,     rout + tA);
        step_one<true>(rB, gwB, b01.x, b01.y, x2, inv, inv4, qout + tB,     rout + tB);
        step_one<true>(rA, gwA, a01.z, a01.w, x2, inv, inv4, qout + tA + 1, rout + tA + 1);
        step_one<true>(rB, gwB, b01.z, b01.w, x2, inv, inv4, qout + tB + 1, rout + tB + 1);
        step_one<true>(rA, gwA, a23.x, a23.y, x2, inv, inv4, qout + tA + 2, rout + tA + 2);
        step_one<true>(rB, gwB, b23.x, b23.y, x2, inv, inv4, qout + tB + 2, rout + tB + 2);
        step_one<true>(rA, gwA, a23.z, a23.w, x2, inv, inv4, qout + tA + 3, rout + tA + 3);
        step_one<true>(rB, gwB, b23.z, b23.w, x2, inv, inv4, qout + tB + 3, rout + tB + 3);
        tA += UNROLL; tB += UNROLL;
    }
}

extern "C" void kernel_launch(void* const* d_in, const int* in_sizes, int n_in,
                              void* d_out, int out_size) {
    const float* x  = (const float*)d_in[0];
    const float* x2 = (const float*)d_in[1];
    const float* x3 = (const float*)d_in[2];
    int T = in_sizes[0] / 4;
    if (T > T_MAX) T = T_MAX;

    int N = WARMUP + T + PAD;
    conv_kernel<<<(N + 255) / 256, 256>>>(x, T);

    int C = T / CHUNK_L;
    int pairs = (C + 1) / 2;
    scan_kernel<<<(pairs + 31) / 32, 32>>>(x2, x3, (float*)d_out, T);
}

// round 5
// speedup vs baseline: 1.2250x; 1.2250x over previous
#include <cuda_runtime.h>

// ---------------------------------------------------------------------------
// RoutingStorage (GR4J routing). FIR conv feeds a nonlinear scalar recurrence
// on routing store r; chunk-parallel scan with warmup (contraction ~0.95/step).
// R5: the scan was bound by 32-line-divergent LDG/STG (each lane's window is
// 256B apart -> 32 L1tex wavefronts per access). Fix: per-block SMEM staging
// with a conflict-free transposed layout (pad d + d>>5 => lane stride 33
// words), and SMEM output staging with a coalesced epilogue.
// ---------------------------------------------------------------------------

#define T_MAX 262144
constexpr int CHUNK_L = 32;    // output steps per chain
constexpr int WARMUP  = 320;   // warmup steps
constexpr int STEPS   = WARMUP + CHUNK_L;           // 352
constexpr int BLK     = 32;    // chunks (threads) per block
constexpr int WSZ     = (BLK - 1) * CHUNK_L + STEPS; // 1344 conv window/block
constexpr int WSZP    = WSZ + WSZ / 32;              // padded
constexpr int OSZ     = BLK * CHUNK_L;               // 1024 outputs/block
constexpr int OSZP    = OSZ + OSZ / 32;
#define PAD 16

// Front-padded with WARMUP zeros: padded index pi corresponds to t = pi-WARMUP.
static __device__ float g_c1[WARMUP + T_MAX + PAD];
static __device__ float g_c2[WARMUP + T_MAX + PAD];

__device__ __forceinline__ float fsqrt_approx(float x) {
    float y; asm("sqrt.approx.f32 %0, %1;" : "=f"(y) : "f"(x)); return y;
}

// Unit-hydrograph ordinates for X4 = 2.5:
__constant__ float c_o1[3] = {0.10119288512538814f, 0.47124051711455807f,
                              0.42756659776005380f};
__constant__ float c_o2[6] = {0.05059644256269407f, 0.23562025855727903f,
                              0.42756659776005380f, 0.23562025855727903f,
                              0.05059644256269407f, 0.0f};

__global__ void conv_kernel(const float* __restrict__ x, int T) {
    int i = blockIdx.x * blockDim.x + threadIdx.x;
    if (i >= WARMUP + T + PAD) return;
    int t = i - WARMUP;
    if (t < 0 || t >= T) { g_c1[i] = 0.0f; g_c2[i] = 0.0f; return; }
    float c1 = 0.0f, c2 = 0.0f;
#pragma unroll
    for (int j = 0; j < 6; ++j) {
        int idx = t - j;
        if (idx >= 0) {
            float4 row = *reinterpret_cast<const float4*>(x + 4 * idx);
            float pr = row.w + (row.x - row.z);   // perc + (p_n - p_s)
            if (j < 3) c1 += c_o1[j] * (0.9f * pr);
            c2 += c_o2[j] * (0.1f * pr);
        }
    }
    g_c1[i] = c1; g_c2[i] = c2;
}

// (1+u)^(-1/4) deg-4 Horner
#define P1 (-0.25f)
#define P2 ( 0.15625f)
#define P3 (-0.1171875f)
#define P4 ( 0.0952148438f)
// (1+u)^(-7/8) deg-3 Horner (off-critical gw branch)
#define Q1 (-0.875f)
#define Q2 ( 0.8203125f)
#define Q3 (-0.7861328125f)

__device__ __forceinline__ int padi(int d) { return d + (d >> 5); }

__global__ void __launch_bounds__(BLK, 1)
scan_kernel(const float* __restrict__ x2p,
            const float* __restrict__ x3p,
            float* __restrict__ out, int T) {
    __shared__ float s1[WSZP];
    __shared__ float s2[WSZP];
    __shared__ float sq[OSZP];
    __shared__ float sr[OSZP];

    int tid = threadIdx.x;
    int t0b = blockIdx.x * OSZ;       // first output timestep of this block
    if (t0b >= T) return;

    // ---- Stage conv window: coalesced global reads -> padded smem ----
    {
        const float* g1 = g_c1 + t0b;   // pi = t0b + d  (pi = t + WARMUP)
        const float* g2 = g_c2 + t0b;
        for (int d = tid; d < WSZ; d += BLK) {
            s1[padi(d)] = g1[d];
            s2[padi(d)] = g2[d];
        }
    }
    __syncthreads();

    const float x2  = __ldg(x2p);
    const float x3  = __ldg(x3p);
    const float inv = 1.0f / x3;
    float inv2 = inv * inv, inv4 = inv2 * inv2;

    float r = 0.0f, gw = 0.0f;            // R_INIT*x3 = 0
    const int base = tid * CHUNK_L;       // this thread's window offset in smem

    // ---- Warmup (c2 path dead; reads only s1) ----
#pragma unroll 8
    for (int i = 0; i < WARMUP; ++i) {
        float c1 = s1[padi(base + i)];
        float s  = fmaxf((r + c1) + gw, 0.0f);
        float s2v = s * s;
        float u  = (s2v * inv4) * s2v;
        float p  = fmaf(u, P4, P3); p = fmaf(u, p, P2);
        p = fmaf(u, p, P1); p = fmaf(u, p, 1.0f);
        float rn = s * p;
        float qq = fmaf(u, Q3, Q2);
        qq = fmaf(u, qq, Q1); qq = fmaf(u, qq, 1.0f);
        float v  = s * inv;
        float sv = fsqrt_approx(v);
        float gs = (x2 * ((v * v) * v)) * sv;
        r  = rn;
        gw = gs * qq;
    }

    // ---- Output phase: results staged to smem ----
#pragma unroll 8
    for (int j = 0; j < CHUNK_L; ++j) {
        int d = base + WARMUP + j;
        float c1 = s1[padi(d)];
        float c2 = s2[padi(d)];
        float s  = fmaxf((r + c1) + gw, 0.0f);
        float qd = fmaxf(c2 + gw, 0.0f);
        float s2v = s * s;
        float u  = (s2v * inv4) * s2v;
        float p  = fmaf(u, P4, P3); p = fmaf(u, p, P2);
        p = fmaf(u, p, P1); p = fmaf(u, p, 1.0f);
        float rn = s * p;
        float qq = fmaf(u, Q3, Q2);
        qq = fmaf(u, qq, Q1); qq = fmaf(u, qq, 1.0f);
        float v  = s * inv;
        float sv = fsqrt_approx(v);
        float gs = (x2 * ((v * v) * v)) * sv;
        int od = base + j;
        sq[padi(od)] = (s - rn) + qd;
        sr[padi(od)] = rn;
        r  = rn;
        gw = gs * qq;
    }
    __syncthreads();

    // ---- Coalesced epilogue ----
    float* __restrict__ qout = out;        // qsim    [0, T)
    float* __restrict__ rout = out + T;    // r_store [T, 2T)
    int lim = T - t0b; if (lim > OSZ) lim = OSZ;
    for (int d = tid; d < lim; d += BLK) {
        qout[t0b + d] = sq[padi(d)];
        rout[t0b + d] = sr[padi(d)];
    }
}

extern "C" void kernel_launch(void* const* d_in, const int* in_sizes, int n_in,
                              void* d_out, int out_size) {
    const float* x  = (const float*)d_in[0];
    const float* x2 = (const float*)d_in[1];
    const float* x3 = (const float*)d_in[2];
    int T = in_sizes[0] / 4;
    if (T > T_MAX) T = T_MAX;

    int N = WARMUP + T + PAD;
    conv_kernel<<<(N + 255) / 256, 256>>>(x, T);

    int nblocks = (T + OSZ - 1) / OSZ;    // 256 for T = 262144
    scan_kernel<<<nblocks, BLK>>>(x2, x3, (float*)d_out, T);
}

// round 6
// speedup vs baseline: 1.8025x; 1.4715x over previous
#include <cuda_runtime.h>

// ---------------------------------------------------------------------------
// RoutingStorage (GR4J routing). FIR conv feeds a nonlinear scalar recurrence;
// chunk-parallel scan with warmup. R6: the scan is bound by in-order
// single-warp issue of a serial ~24-instr step body (per-step ~150cyc vs
// 44-cyc dep chain). Fix: interleave TWO independent chains per thread
// (program-order A/B alternation fills dependency stalls), fed from
// conflict-free padded SMEM (R5 infra). Warmup cut 320->240 (contraction
// ~0.962/step; predicted residual ~2e-4 rel, threshold 1e-3).
// ---------------------------------------------------------------------------

#define T_MAX 262144
constexpr int CHUNK_L = 16;    // output steps per chain
constexpr int WARMUP  = 240;   // warmup steps
constexpr int STEPS   = WARMUP + CHUNK_L;            // 256
constexpr int BLK     = 32;    // threads per block, each runs 2 chains
constexpr int OSZ     = BLK * 2 * CHUNK_L;           // 1024 outputs/block
constexpr int OSZP    = OSZ + OSZ / 32;
constexpr int WSZ     = (BLK - 1) * 32 + 16 + STEPS; // 1264 conv window/block
constexpr int WSZP    = WSZ + WSZ / 32 + 1;
#define PAD 16

// Front-padded with WARMUP zeros: padded index pi corresponds to t = pi-WARMUP.
static __device__ float g_c1[WARMUP + T_MAX + PAD];
static __device__ float g_c2[WARMUP + T_MAX + PAD];

__device__ __forceinline__ float fsqrt_approx(float x) {
    float y; asm("sqrt.approx.f32 %0, %1;" : "=f"(y) : "f"(x)); return y;
}

// Unit-hydrograph ordinates for X4 = 2.5:
__constant__ float c_o1[3] = {0.10119288512538814f, 0.47124051711455807f,
                              0.42756659776005380f};
__constant__ float c_o2[6] = {0.05059644256269407f, 0.23562025855727903f,
                              0.42756659776005380f, 0.23562025855727903f,
                              0.05059644256269407f, 0.0f};

__global__ void conv_kernel(const float* __restrict__ x, int T) {
    int i = blockIdx.x * blockDim.x + threadIdx.x;
    if (i >= WARMUP + T + PAD) return;
    int t = i - WARMUP;
    if (t < 0 || t >= T) { g_c1[i] = 0.0f; g_c2[i] = 0.0f; return; }
    float c1 = 0.0f, c2 = 0.0f;
#pragma unroll
    for (int j = 0; j < 6; ++j) {
        int idx = t - j;
        if (idx >= 0) {
            float4 row = *reinterpret_cast<const float4*>(x + 4 * idx);
            float pr = row.w + (row.x - row.z);   // perc + (p_n - p_s)
            if (j < 3) c1 += c_o1[j] * (0.9f * pr);
            c2 += c_o2[j] * (0.1f * pr);
        }
    }
    g_c1[i] = c1; g_c2[i] = c2;
}

// (1+u)^(-1/4) deg-4 Horner
#define P1 (-0.25f)
#define P2 ( 0.15625f)
#define P3 (-0.1171875f)
#define P4 ( 0.0952148438f)
// (1+u)^(-7/8) deg-3 Horner (off-critical gw branch)
#define Q1 (-0.875f)
#define Q2 ( 0.8203125f)
#define Q3 (-0.7861328125f)

__device__ __forceinline__ int padi(int d) { return d + (d >> 5); }

// One recurrence step; carries (r, gw). STORE => also produce q, rn.
template<bool STORE>
__device__ __forceinline__ void step(float& r, float& gw, float c1, float c2,
                                     float x2, float inv, float inv4,
                                     float& q, float& rst) {
    float s   = fmaxf(r + (c1 + gw), 0.0f);
    float s2v = s * s;
    float u   = (s2v * inv4) * s2v;                 // (s/x3)^4
    float p   = fmaf(u, P4, P3); p = fmaf(u, p, P2);
    p = fmaf(u, p, P1); p = fmaf(u, p, 1.0f);       // (1+u)^(-1/4)
    float rn  = s * p;
    float qq  = fmaf(u, Q3, Q2);
    qq = fmaf(u, qq, Q1); qq = fmaf(u, qq, 1.0f);   // (1+u)^(-7/8)
    float v   = s * inv;
    float sv  = fsqrt_approx(v);
    float gs  = (x2 * ((v * v) * v)) * sv;          // x2*(s/x3)^3.5
    if (STORE) {
        float qd = fmaxf(c2 + gw, 0.0f);
        q   = (s - rn) + qd;
        rst = rn;
    }
    r  = rn;
    gw = gs * qq;                                   // x2*(rn/x3)^3.5
}

__global__ void __launch_bounds__(BLK, 1)
scan_kernel(const float* __restrict__ x2p,
            const float* __restrict__ x3p,
            float* __restrict__ out, int T) {
    __shared__ float s1[WSZP];
    __shared__ float s2[WSZP];
    __shared__ float sq[OSZP];
    __shared__ float sr[OSZP];

    int tid = threadIdx.x;
    int t0b = blockIdx.x * OSZ;       // first output timestep of this block
    if (t0b >= T) return;

    // ---- Stage conv window: coalesced global reads -> padded smem ----
    {
        const float* g1 = g_c1 + t0b;
        const float* g2 = g_c2 + t0b;
        for (int d = tid; d < WSZ; d += BLK) {
            s1[padi(d)] = g1[d];
            s2[padi(d)] = g2[d];
        }
    }
    __syncthreads();

    const float x2  = __ldg(x2p);
    const float x3  = __ldg(x3p);
    const float inv = 1.0f / x3;
    float inv2 = inv * inv, inv4 = inv2 * inv2;

    // Thread runs chains A (window offset 32*tid) and B (offset 32*tid+16).
    const int baseA = tid * 32;
    const int baseB = baseA + 16;

    float rA = 0.0f, gwA = 0.0f;
    float rB = 0.0f, gwB = 0.0f;
    float qdum, rdum;

    // ---- Warmup: interleaved A/B, no stores (c2 path dead) ----
#pragma unroll 4
    for (int i = 0; i < WARMUP; ++i) {
        float cA = s1[padi(baseA + i)];
        float cB = s1[padi(baseB + i)];
        step<false>(rA, gwA, cA, 0.0f, x2, inv, inv4, qdum, rdum);
        step<false>(rB, gwB, cB, 0.0f, x2, inv, inv4, qdum, rdum);
    }

    // ---- Output phase: interleaved, results staged to smem ----
#pragma unroll
    for (int j = 0; j < CHUNK_L; ++j) {
        int dA = baseA + WARMUP + j;
        int dB = baseB + WARMUP + j;
        float c1A = s1[padi(dA)], c2A = s2[padi(dA)];
        float c1B = s1[padi(dB)], c2B = s2[padi(dB)];
        float qA, rnA, qB, rnB;
        step<true>(rA, gwA, c1A, c2A, x2, inv, inv4, qA, rnA);
        step<true>(rB, gwB, c1B, c2B, x2, inv, inv4, qB, rnB);
        int oA = baseA + j, oB = baseB + j;
        sq[padi(oA)] = qA;  sr[padi(oA)] = rnA;
        sq[padi(oB)] = qB;  sr[padi(oB)] = rnB;
    }
    __syncthreads();

    // ---- Coalesced epilogue ----
    float* __restrict__ qout = out;        // qsim    [0, T)
    float* __restrict__ rout = out + T;    // r_store [T, 2T)
    int lim = T - t0b; if (lim > OSZ) lim = OSZ;
    for (int d = tid; d < lim; d += BLK) {
        qout[t0b + d] = sq[padi(d)];
        rout[t0b + d] = sr[padi(d)];
    }
}

extern "C" void kernel_launch(void* const* d_in, const int* in_sizes, int n_in,
                              void* d_out, int out_size) {
    const float* x  = (const float*)d_in[0];
    const float* x2 = (const float*)d_in[1];
    const float* x3 = (const float*)d_in[2];
    int T = in_sizes[0] / 4;
    if (T > T_MAX) T = T_MAX;

    int N = WARMUP + T + PAD;
    conv_kernel<<<(N + 255) / 256, 256>>>(x, T);

    int nblocks = (T + OSZ - 1) / OSZ;    // 256 for T = 262144
    scan_kernel<<<nblocks, BLK>>>(x2, x3, (float*)d_out, T);
}